// round 10
// baseline (speedup 1.0000x reference)
#include <cuda_runtime.h>
#include <cuda_fp16.h>
#include <cstdint>

#define NN 50000
#define EE 800000
#define CC 512     // H*HID
#define HH 8
#define FF 64

// ---------------- scratch (device globals; no allocation allowed) ----------
__device__ __half g_feat[(size_t)NN * CC];  // 51.2 MB projected features (fp16)
__device__ float g_el[NN * HH];
__device__ float g_er[NN * HH];
__device__ float g_h[NN * FF];              // layer activations (fp32)
__device__ int   g_rowptr[NN + 1];
__device__ int   g_cnt[NN];
__device__ int   g_fill[NN];
__device__ int   g_col[EE];                 // src ids grouped by dst (CSR order)

// ---------------- CSR build ------------------------------------------------
__global__ void k_zero() {
    int i = blockIdx.x * blockDim.x + threadIdx.x;
    if (i < NN) { g_cnt[i] = 0; g_fill[i] = 0; }
}

__global__ void k_hist(const int* __restrict__ dst) {
    int e = blockIdx.x * blockDim.x + threadIdx.x;
    if (e < EE) atomicAdd(&g_cnt[dst[e]], 1);
}

__global__ void k_scan() {
    __shared__ int sh[1024];
    __shared__ int s_off;
    int tid = threadIdx.x;
    if (tid == 0) s_off = 0;
    __syncthreads();
    for (int base = 0; base < NN; base += 1024) {
        int idx = base + tid;
        int orig = (idx < NN) ? g_cnt[idx] : 0;
        int v = orig;
        sh[tid] = v;
        __syncthreads();
        for (int off = 1; off < 1024; off <<= 1) {
            int add = (tid >= off) ? sh[tid - off] : 0;
            __syncthreads();
            v += add; sh[tid] = v;
            __syncthreads();
        }
        int myoff = s_off;
        if (idx < NN) g_rowptr[idx] = myoff + (v - orig);
        __syncthreads();
        if (tid == 1023) s_off = myoff + v;
        __syncthreads();
    }
    if (tid == 0) g_rowptr[NN] = s_off;
}

__global__ void k_scatter(const int* __restrict__ src, const int* __restrict__ dst) {
    int e = blockIdx.x * blockDim.x + threadIdx.x;
    if (e < EE) {
        int d = dst[e];
        int pos = g_rowptr[d] + atomicAdd(&g_fill[d], 1);
        g_col[pos] = src[e];
    }
}

// ---------------- fp16 tensor-core GEMM + fused el/er ----------------------
__device__ __forceinline__ uint32_t pk(float x, float y) {
    __half2 h = __floats2half2_rn(x, y);
    return *reinterpret_cast<uint32_t*>(&h);
}

__device__ __forceinline__ void store_c(float* C, size_t idx, float v) { C[idx] = v; }
__device__ __forceinline__ void store_c(__half* C, size_t idx, float v) { C[idx] = __float2half_rn(v); }

template <typename OutT>
__global__ __launch_bounds__(256, 2) void k_gemm_tc(
    const float* __restrict__ A, const float* __restrict__ B,
    const float* __restrict__ bias, OutT* __restrict__ C,
    const float* __restrict__ al, const float* __restrict__ ar,
    int M, int NCol, int K)
{
    __shared__ uint32_t As2[2 * 8 * 32 * 4];   // 8 KB
    __shared__ uint32_t Bs2[2 * 8 * 32 * 2];   // 4 KB
    __shared__ float s_el[128], s_er[128];
    const int tid = threadIdx.x;
    const int lane = tid & 31, wid = tid >> 5;
    const int wm = wid & 3, wn = wid >> 2;
    const int m0 = blockIdx.y * 128, n0 = blockIdx.x * 64;

    float acc[2][4][4];
#pragma unroll
    for (int im = 0; im < 2; im++)
#pragma unroll
        for (int in = 0; in < 4; in++)
#pragma unroll
            for (int q = 0; q < 4; q++) acc[im][in][q] = 0.f;

    float4 rA[4], rB[2];

#pragma unroll
    for (int i = 0; i < 4; i++) {
        int idx = tid + 256 * i;
        int row = idx >> 3, c0 = (idx & 7) << 2;
        int gr = m0 + row;
        rA[i] = (gr < M) ? *(const float4*)(A + (size_t)gr * K + c0)
                         : make_float4(0.f, 0.f, 0.f, 0.f);
    }
#pragma unroll
    for (int i = 0; i < 2; i++) {
        int idx = tid + 256 * i;
        int row = idx >> 3, c0 = (idx & 7) << 2;
        rB[i] = *(const float4*)(B + (size_t)(n0 + row) * K + c0);
    }

    for (int kt = 0; kt < K; kt += 32) {
        __syncthreads();
#pragma unroll
        for (int i = 0; i < 4; i++) {
            int idx = tid + 256 * i;
            int row = idx >> 3, c0 = (idx & 7) << 2;
            int ks = c0 >> 4, ck = c0 & 15;
            int q0 = ck >> 3, tig0 = (ck & 7) >> 1;
            int mt = row >> 4, rr = row & 15;
            int q1 = rr >> 3, gid = rr & 7;
            int reg = (q1 + 2 * q0) ^ (ks << 1);
            int sb = ((ks * 8 + mt) * 32 + gid * 4);
            As2[(sb + tig0) * 4 + reg]     = pk(rA[i].x, rA[i].y);
            As2[(sb + tig0 + 1) * 4 + reg] = pk(rA[i].z, rA[i].w);
        }
#pragma unroll
        for (int i = 0; i < 2; i++) {
            int idx = tid + 256 * i;
            int row = idx >> 3, c0 = (idx & 7) << 2;
            int ks = c0 >> 4, ck = c0 & 15;
            int q0 = ck >> 3, tig0 = (ck & 7) >> 1;
            int nt = row >> 3, gid = row & 7;
            int l0 = gid * 4 + tig0;
            int base = (ks * 8 + nt) * 32;
            Bs2[(base + ((l0 + ks * 2) & 31)) * 2 + q0]     = pk(rB[i].x, rB[i].y);
            Bs2[(base + ((l0 + 1 + ks * 2) & 31)) * 2 + q0] = pk(rB[i].z, rB[i].w);
        }
        __syncthreads();

        if (kt + 32 < K) {
#pragma unroll
            for (int i = 0; i < 4; i++) {
                int idx = tid + 256 * i;
                int row = idx >> 3, c0 = (idx & 7) << 2;
                int gr = m0 + row;
                rA[i] = (gr < M) ? *(const float4*)(A + (size_t)gr * K + kt + 32 + c0)
                                 : make_float4(0.f, 0.f, 0.f, 0.f);
            }
#pragma unroll
            for (int i = 0; i < 2; i++) {
                int idx = tid + 256 * i;
                int row = idx >> 3, c0 = (idx & 7) << 2;
                rB[i] = *(const float4*)(B + (size_t)(n0 + row) * K + kt + 32 + c0);
            }
        }

#pragma unroll
        for (int ks = 0; ks < 2; ks++) {
            uint32_t a[2][4];
#pragma unroll
            for (int im = 0; im < 2; im++) {
                uint4 v = *(const uint4*)(As2 + ((ks * 8 + wm * 2 + im) * 32 + lane) * 4);
                uint32_t vc[4] = {v.x, v.y, v.z, v.w};
#pragma unroll
                for (int j = 0; j < 4; j++) a[im][j] = vc[j ^ (ks << 1)];
            }
            uint32_t b[4][2];
#pragma unroll
            for (int in = 0; in < 4; in++) {
                uint2 u = *(const uint2*)(Bs2 + ((ks * 8 + wn * 4 + in) * 32 + ((lane + ks * 2) & 31)) * 2);
                b[in][0] = u.x; b[in][1] = u.y;
            }
#pragma unroll
            for (int im = 0; im < 2; im++)
#pragma unroll
                for (int in = 0; in < 4; in++)
                    asm volatile(
                        "mma.sync.aligned.m16n8k16.row.col.f32.f16.f16.f32 "
                        "{%0,%1,%2,%3},{%4,%5,%6,%7},{%8,%9},{%0,%1,%2,%3};"
                        : "+f"(acc[im][in][0]), "+f"(acc[im][in][1]),
                          "+f"(acc[im][in][2]), "+f"(acc[im][in][3])
                        : "r"(a[im][0]), "r"(a[im][1]), "r"(a[im][2]), "r"(a[im][3]),
                          "r"(b[in][0]), "r"(b[in][1]));
        }
    }

    int gid = lane >> 2, tig = lane & 3;
#pragma unroll
    for (int im = 0; im < 2; im++) {
        int r = m0 + wm * 32 + im * 16 + gid;
#pragma unroll
        for (int in = 0; in < 4; in++) {
            int c = n0 + wn * 32 + in * 8 + tig * 2;
            float b0v = bias ? bias[c] : 0.f;
            float b1v = bias ? bias[c + 1] : 0.f;
            if (r < M) {
                store_c(C, (size_t)r * NCol + c,     acc[im][in][0] + b0v);
                store_c(C, (size_t)r * NCol + c + 1, acc[im][in][1] + b1v);
            }
            if (r + 8 < M) {
                store_c(C, (size_t)(r + 8) * NCol + c,     acc[im][in][2] + b0v);
                store_c(C, (size_t)(r + 8) * NCol + c + 1, acc[im][in][3] + b1v);
            }
        }
    }

    if (al != nullptr) {
        int head = blockIdx.x;
        const float* alh = al + head * FF;
        const float* arh = ar + head * FF;
        float sl[2][2] = {}, sr[2][2] = {};
#pragma unroll
        for (int im = 0; im < 2; im++)
#pragma unroll
            for (int in = 0; in < 4; in++) {
                int cc0 = wn * 32 + in * 8 + tig * 2;
                float a0 = alh[cc0], a1 = alh[cc0 + 1];
                float r0 = arh[cc0], r1 = arh[cc0 + 1];
                sl[im][0] += acc[im][in][0] * a0 + acc[im][in][1] * a1;
                sl[im][1] += acc[im][in][2] * a0 + acc[im][in][3] * a1;
                sr[im][0] += acc[im][in][0] * r0 + acc[im][in][1] * r1;
                sr[im][1] += acc[im][in][2] * r0 + acc[im][in][3] * r1;
            }
#pragma unroll
        for (int o = 1; o <= 2; o <<= 1)
#pragma unroll
            for (int im = 0; im < 2; im++)
#pragma unroll
                for (int hq = 0; hq < 2; hq++) {
                    sl[im][hq] += __shfl_xor_sync(0xffffffffu, sl[im][hq], o);
                    sr[im][hq] += __shfl_xor_sync(0xffffffffu, sr[im][hq], o);
                }
        __syncthreads();
        if (wn == 0 && tig == 0) {
#pragma unroll
            for (int im = 0; im < 2; im++) {
                int rl = wm * 32 + im * 16 + gid;
                s_el[rl] = sl[im][0];     s_er[rl] = sr[im][0];
                s_el[rl + 8] = sl[im][1]; s_er[rl + 8] = sr[im][1];
            }
        }
        __syncthreads();
        if (wn == 1 && tig == 0) {
#pragma unroll
            for (int im = 0; im < 2; im++) {
                int rl = wm * 32 + im * 16 + gid;
                int r = m0 + rl;
                if (r < M) {
                    g_el[r * HH + head] = s_el[rl] + sl[im][0];
                    g_er[r * HH + head] = s_er[rl] + sr[im][0];
                }
                if (r + 8 < M) {
                    g_el[(r + 8) * HH + head] = s_el[rl + 8] + sl[im][1];
                    g_er[(r + 8) * HH + head] = s_er[rl + 8] + sr[im][1];
                }
            }
        }
    }
}

// ---------------- aggregate: block per dst, warp per head ------------------
// Chunked staging: per 64-edge chunk, all 256 threads cooperatively load col
// and the edge's 8-float el row (1 line access/edge), compute
// p = exp(leaky(el+er)) into smem. The per-warp loop then carries only the
// feat gather; p/s reads are conflict-free smem broadcasts.
__global__ __launch_bounds__(256) void k_agg(const float* __restrict__ bias, float* __restrict__ y) {
    int n = blockIdx.x;
    int tid = threadIdx.x, w = tid >> 5, lane = tid & 31;
    int sub = lane >> 3, j = lane & 7;
    __shared__ float s_acc[HH][FF];
    __shared__ float s_er[HH];
    __shared__ float s_p[64][HH];
    __shared__ int   s_col[64];
    int beg = g_rowptr[n], end = g_rowptr[n + 1];
    int deg = end - beg;

    if (tid < HH) s_er[tid] = __ldg(&g_er[n * HH + tid]);
    __syncthreads();

    float acc[8] = {};
    float ssum = 0.f;

    for (int cb = 0; cb < deg; cb += 64) {
        int cnt = min(64, deg - cb);
        // ---- stage col + p for this chunk (e = tid>>2, 2 heads per thread)
        {
            int e = tid >> 2, part = tid & 3;
            int s = 0;
            float p0 = 0.f, p1 = 0.f;
            if (e < cnt) {
                s = __ldg(&g_col[beg + cb + e]);
                float2 el2 = *(const float2*)&g_el[s * HH + part * 2];
                float e0 = el2.x + s_er[part * 2];
                float e1 = el2.y + s_er[part * 2 + 1];
                e0 = e0 > 0.f ? e0 : 0.2f * e0;
                e1 = e1 > 0.f ? e1 : 0.2f * e1;
                p0 = __expf(e0);
                p1 = __expf(e1);
            }
            if (part == 0) s_col[e] = s;
            s_p[e][part * 2] = p0;
            s_p[e][part * 2 + 1] = p1;
        }
        __syncthreads();

        // ---- per-warp: 4 edges/iter, feat gather only
        int niter = (cnt + 3) >> 2;
#pragma unroll 2
        for (int i = 0; i < niter; i++) {
            int e = i * 4 + sub;                 // < 64 always
            int s = s_col[e];
            float p = s_p[e][w];
            uint4 v = *(const uint4*)(g_feat + (size_t)s * CC + w * FF + j * 8);
            float2 f0 = __half22float2(*(const __half2*)&v.x);
            float2 f1 = __half22float2(*(const __half2*)&v.y);
            float2 f2 = __half22float2(*(const __half2*)&v.z);
            float2 f3 = __half22float2(*(const __half2*)&v.w);
            acc[0] += p * f0.x; acc[1] += p * f0.y;
            acc[2] += p * f1.x; acc[3] += p * f1.y;
            acc[4] += p * f2.x; acc[5] += p * f2.y;
            acc[6] += p * f3.x; acc[7] += p * f3.y;
            ssum += p;
        }
        __syncthreads();
    }

    // reduce the 4 edge-subgroups (lane bits 3,4)
#pragma unroll
    for (int o = 8; o <= 16; o <<= 1) {
        ssum += __shfl_xor_sync(0xffffffffu, ssum, o);
#pragma unroll
        for (int k = 0; k < 8; k++) acc[k] += __shfl_xor_sync(0xffffffffu, acc[k], o);
    }
    float inv = (deg > 0) ? 1.0f / ssum : 0.f;
    if (sub == 0) {
#pragma unroll
        for (int k = 0; k < 8; k++)
            s_acc[w][j * 8 + k] = acc[k] * inv + bias[w * FF + j * 8 + k];
    }
    __syncthreads();

    // sum heads + leaky(0.01)
    if (tid < FF) {
        float v = 0.f;
#pragma unroll
        for (int hh = 0; hh < HH; hh++) v += s_acc[hh][tid];
        v = v > 0.f ? v : 0.01f * v;
        y[(size_t)n * FF + tid] = v;
    }
}

// ---------------- launcher -------------------------------------------------
extern "C" void kernel_launch(void* const* d_in, const int* in_sizes, int n_in,
                              void* d_out, int out_size) {
    const float* x   = (const float*)d_in[0];
    const int*   src = (const int*)d_in[1];
    const int*   dst = (const int*)d_in[2];
    const float* W1  = (const float*)d_in[3];
    const float* al1 = (const float*)d_in[4];
    const float* ar1 = (const float*)d_in[5];
    const float* b1  = (const float*)d_in[6];
    const float* W2  = (const float*)d_in[7];
    const float* al2 = (const float*)d_in[8];
    const float* ar2 = (const float*)d_in[9];
    const float* b2  = (const float*)d_in[10];
    const float* W3  = (const float*)d_in[11];
    const float* al3 = (const float*)d_in[12];
    const float* ar3 = (const float*)d_in[13];
    const float* b3  = (const float*)d_in[14];
    const float* Wm  = (const float*)d_in[15];
    const float* bm  = (const float*)d_in[16];
    float* out = (float*)d_out;

    __half* feat_p;
    float* h_p;
    cudaGetSymbolAddress((void**)&feat_p, g_feat);
    cudaGetSymbolAddress((void**)&h_p, g_h);

    // CSR by dst (rebuilt every call; identical work each time)
    k_zero<<<(NN + 255) / 256, 256>>>();
    k_hist<<<(EE + 255) / 256, 256>>>(dst);
    k_scan<<<1, 1024>>>();
    k_scatter<<<(EE + 255) / 256, 256>>>(src, dst);

    dim3 gproj(CC / 64, (NN + 127) / 128);

    // layer 1 (K=128)
    k_gemm_tc<__half><<<gproj, 256>>>(x, W1, nullptr, feat_p, al1, ar1, NN, CC, 128);
    k_agg<<<NN, 256>>>(b1, h_p);

    // layer 2 (K=64)
    k_gemm_tc<__half><<<gproj, 256>>>(h_p, W2, nullptr, feat_p, al2, ar2, NN, CC, 64);
    k_agg<<<NN, 256>>>(b2, h_p);

    // layer 3 (K=64)
    k_gemm_tc<__half><<<gproj, 256>>>(h_p, W3, nullptr, feat_p, al3, ar3, NN, CC, 64);
    k_agg<<<NN, 256>>>(b3, h_p);

    // final linear: out = h @ Wm^T + bm  [N,OUT]
    k_gemm_tc<float><<<dim3(1, (NN + 127) / 128), 256>>>(h_p, Wm, bm, out,
                                                         nullptr, nullptr, NN, FF, FF);
}

// round 11
// speedup vs baseline: 1.3039x; 1.3039x over previous
#include <cuda_runtime.h>
#include <cuda_fp16.h>
#include <cstdint>

#define NN 50000
#define EE 800000
#define CC 512     // H*HID
#define HH 8
#define FF 64

// ---------------- scratch (device globals; no allocation allowed) ----------
__device__ __half g_feat[(size_t)NN * CC];  // 51.2 MB projected features (fp16)
__device__ float g_el[NN * HH];
__device__ float g_er[NN * HH];
__device__ float g_h[NN * FF];              // layer activations (fp32)
__device__ int   g_rowptr[NN + 1];
__device__ int   g_cnt[NN];
__device__ int   g_fill[NN];
__device__ int   g_col[EE];                 // src ids grouped by dst (CSR order)

// ---------------- CSR build ------------------------------------------------
__global__ void k_hist(const int* __restrict__ dst) {
    int e = blockIdx.x * blockDim.x + threadIdx.x;
    if (e < EE) atomicAdd(&g_cnt[dst[e]], 1);
}

__global__ void k_scan() {
    __shared__ int sh[1024];
    __shared__ int s_off;
    int tid = threadIdx.x;
    if (tid == 0) s_off = 0;
    __syncthreads();
    for (int base = 0; base < NN; base += 1024) {
        int idx = base + tid;
        int orig = (idx < NN) ? g_cnt[idx] : 0;
        int v = orig;
        sh[tid] = v;
        __syncthreads();
        for (int off = 1; off < 1024; off <<= 1) {
            int add = (tid >= off) ? sh[tid - off] : 0;
            __syncthreads();
            v += add; sh[tid] = v;
            __syncthreads();
        }
        int myoff = s_off;
        if (idx < NN) g_rowptr[idx] = myoff + (v - orig);
        __syncthreads();
        if (tid == 1023) s_off = myoff + v;
        __syncthreads();
    }
    if (tid == 0) g_rowptr[NN] = s_off;
}

__global__ void k_scatter(const int* __restrict__ src, const int* __restrict__ dst) {
    int e = blockIdx.x * blockDim.x + threadIdx.x;
    if (e < EE) {
        int d = dst[e];
        int pos = g_rowptr[d] + atomicAdd(&g_fill[d], 1);
        g_col[pos] = src[e];
    }
}

// ---------------- fp16 tensor-core GEMM + fused el/er ----------------------
__device__ __forceinline__ uint32_t pk(float x, float y) {
    __half2 h = __floats2half2_rn(x, y);
    return *reinterpret_cast<uint32_t*>(&h);
}

__device__ __forceinline__ void store_c(float* C, size_t idx, float v) { C[idx] = v; }
__device__ __forceinline__ void store_c(__half* C, size_t idx, float v) { C[idx] = __float2half_rn(v); }

template <typename OutT>
__global__ __launch_bounds__(256, 2) void k_gemm_tc(
    const float* __restrict__ A, const float* __restrict__ B,
    const float* __restrict__ bias, OutT* __restrict__ C,
    const float* __restrict__ al, const float* __restrict__ ar,
    int M, int NCol, int K)
{
    __shared__ uint32_t As2[2 * 8 * 32 * 4];   // 8 KB
    __shared__ uint32_t Bs2[2 * 8 * 32 * 2];   // 4 KB
    __shared__ float s_el[128], s_er[128];
    const int tid = threadIdx.x;
    const int lane = tid & 31, wid = tid >> 5;
    const int wm = wid & 3, wn = wid >> 2;
    const int m0 = blockIdx.y * 128, n0 = blockIdx.x * 64;

    float acc[2][4][4];
#pragma unroll
    for (int im = 0; im < 2; im++)
#pragma unroll
        for (int in = 0; in < 4; in++)
#pragma unroll
            for (int q = 0; q < 4; q++) acc[im][in][q] = 0.f;

    float4 rA[4], rB[2];

#pragma unroll
    for (int i = 0; i < 4; i++) {
        int idx = tid + 256 * i;
        int row = idx >> 3, c0 = (idx & 7) << 2;
        int gr = m0 + row;
        rA[i] = (gr < M) ? *(const float4*)(A + (size_t)gr * K + c0)
                         : make_float4(0.f, 0.f, 0.f, 0.f);
    }
#pragma unroll
    for (int i = 0; i < 2; i++) {
        int idx = tid + 256 * i;
        int row = idx >> 3, c0 = (idx & 7) << 2;
        rB[i] = *(const float4*)(B + (size_t)(n0 + row) * K + c0);
    }

    for (int kt = 0; kt < K; kt += 32) {
        __syncthreads();
#pragma unroll
        for (int i = 0; i < 4; i++) {
            int idx = tid + 256 * i;
            int row = idx >> 3, c0 = (idx & 7) << 2;
            int ks = c0 >> 4, ck = c0 & 15;
            int q0 = ck >> 3, tig0 = (ck & 7) >> 1;
            int mt = row >> 4, rr = row & 15;
            int q1 = rr >> 3, gid = rr & 7;
            int reg = (q1 + 2 * q0) ^ (ks << 1);
            int sb = ((ks * 8 + mt) * 32 + gid * 4);
            As2[(sb + tig0) * 4 + reg]     = pk(rA[i].x, rA[i].y);
            As2[(sb + tig0 + 1) * 4 + reg] = pk(rA[i].z, rA[i].w);
        }
#pragma unroll
        for (int i = 0; i < 2; i++) {
            int idx = tid + 256 * i;
            int row = idx >> 3, c0 = (idx & 7) << 2;
            int ks = c0 >> 4, ck = c0 & 15;
            int q0 = ck >> 3, tig0 = (ck & 7) >> 1;
            int nt = row >> 3, gid = row & 7;
            int l0 = gid * 4 + tig0;
            int base = (ks * 8 + nt) * 32;
            Bs2[(base + ((l0 + ks * 2) & 31)) * 2 + q0]     = pk(rB[i].x, rB[i].y);
            Bs2[(base + ((l0 + 1 + ks * 2) & 31)) * 2 + q0] = pk(rB[i].z, rB[i].w);
        }
        __syncthreads();

        if (kt + 32 < K) {
#pragma unroll
            for (int i = 0; i < 4; i++) {
                int idx = tid + 256 * i;
                int row = idx >> 3, c0 = (idx & 7) << 2;
                int gr = m0 + row;
                rA[i] = (gr < M) ? *(const float4*)(A + (size_t)gr * K + kt + 32 + c0)
                                 : make_float4(0.f, 0.f, 0.f, 0.f);
            }
#pragma unroll
            for (int i = 0; i < 2; i++) {
                int idx = tid + 256 * i;
                int row = idx >> 3, c0 = (idx & 7) << 2;
                rB[i] = *(const float4*)(B + (size_t)(n0 + row) * K + kt + 32 + c0);
            }
        }

#pragma unroll
        for (int ks = 0; ks < 2; ks++) {
            uint32_t a[2][4];
#pragma unroll
            for (int im = 0; im < 2; im++) {
                uint4 v = *(const uint4*)(As2 + ((ks * 8 + wm * 2 + im) * 32 + lane) * 4);
                uint32_t vc[4] = {v.x, v.y, v.z, v.w};
#pragma unroll
                for (int j = 0; j < 4; j++) a[im][j] = vc[j ^ (ks << 1)];
            }
            uint32_t b[4][2];
#pragma unroll
            for (int in = 0; in < 4; in++) {
                uint2 u = *(const uint2*)(Bs2 + ((ks * 8 + wn * 4 + in) * 32 + ((lane + ks * 2) & 31)) * 2);
                b[in][0] = u.x; b[in][1] = u.y;
            }
#pragma unroll
            for (int im = 0; im < 2; im++)
#pragma unroll
                for (int in = 0; in < 4; in++)
                    asm volatile(
                        "mma.sync.aligned.m16n8k16.row.col.f32.f16.f16.f32 "
                        "{%0,%1,%2,%3},{%4,%5,%6,%7},{%8,%9},{%0,%1,%2,%3};"
                        : "+f"(acc[im][in][0]), "+f"(acc[im][in][1]),
                          "+f"(acc[im][in][2]), "+f"(acc[im][in][3])
                        : "r"(a[im][0]), "r"(a[im][1]), "r"(a[im][2]), "r"(a[im][3]),
                          "r"(b[in][0]), "r"(b[in][1]));
        }
    }

    int gid = lane >> 2, tig = lane & 3;
#pragma unroll
    for (int im = 0; im < 2; im++) {
        int r = m0 + wm * 32 + im * 16 + gid;
#pragma unroll
        for (int in = 0; in < 4; in++) {
            int c = n0 + wn * 32 + in * 8 + tig * 2;
            float b0v = bias ? bias[c] : 0.f;
            float b1v = bias ? bias[c + 1] : 0.f;
            if (r < M) {
                store_c(C, (size_t)r * NCol + c,     acc[im][in][0] + b0v);
                store_c(C, (size_t)r * NCol + c + 1, acc[im][in][1] + b1v);
            }
            if (r + 8 < M) {
                store_c(C, (size_t)(r + 8) * NCol + c,     acc[im][in][2] + b0v);
                store_c(C, (size_t)(r + 8) * NCol + c + 1, acc[im][in][3] + b1v);
            }
        }
    }

    if (al != nullptr) {
        int head = blockIdx.x;
        const float* alh = al + head * FF;
        const float* arh = ar + head * FF;
        float sl[2][2] = {}, sr[2][2] = {};
#pragma unroll
        for (int im = 0; im < 2; im++)
#pragma unroll
            for (int in = 0; in < 4; in++) {
                int cc0 = wn * 32 + in * 8 + tig * 2;
                float a0 = alh[cc0], a1 = alh[cc0 + 1];
                float r0 = arh[cc0], r1 = arh[cc0 + 1];
                sl[im][0] += acc[im][in][0] * a0 + acc[im][in][1] * a1;
                sl[im][1] += acc[im][in][2] * a0 + acc[im][in][3] * a1;
                sr[im][0] += acc[im][in][0] * r0 + acc[im][in][1] * r1;
                sr[im][1] += acc[im][in][2] * r0 + acc[im][in][3] * r1;
            }
#pragma unroll
        for (int o = 1; o <= 2; o <<= 1)
#pragma unroll
            for (int im = 0; im < 2; im++)
#pragma unroll
                for (int hq = 0; hq < 2; hq++) {
                    sl[im][hq] += __shfl_xor_sync(0xffffffffu, sl[im][hq], o);
                    sr[im][hq] += __shfl_xor_sync(0xffffffffu, sr[im][hq], o);
                }
        __syncthreads();
        if (wn == 0 && tig == 0) {
#pragma unroll
            for (int im = 0; im < 2; im++) {
                int rl = wm * 32 + im * 16 + gid;
                s_el[rl] = sl[im][0];     s_er[rl] = sr[im][0];
                s_el[rl + 8] = sl[im][1]; s_er[rl + 8] = sr[im][1];
            }
        }
        __syncthreads();
        if (wn == 1 && tig == 0) {
#pragma unroll
            for (int im = 0; im < 2; im++) {
                int rl = wm * 32 + im * 16 + gid;
                int r = m0 + rl;
                if (r < M) {
                    g_el[r * HH + head] = s_el[rl] + sl[im][0];
                    g_er[r * HH + head] = s_er[rl] + sr[im][0];
                }
                if (r + 8 < M) {
                    g_el[(r + 8) * HH + head] = s_el[rl + 8] + sl[im][1];
                    g_er[(r + 8) * HH + head] = s_er[rl + 8] + sr[im][1];
                }
            }
        }
    }
}

// ---------------- aggregate: warp per node, all 8 heads in-warp ------------
// Lane l owns head l>>3 feats [(l&7)*8,+8) via row4[l], and head (l>>3)+4 via
// row4[32+l] (fully dense 512B feat load instructions). Lanes 0-7 compute the
// 8 heads' exp-weights once per edge (1 expf per edge-head); shfl broadcasts.
// No smem, no barriers, no loop-end accumulator reduction.
__global__ __launch_bounds__(256) void k_agg(const float* __restrict__ bias, float* __restrict__ y) {
    int n = blockIdx.x * 8 + (threadIdx.x >> 5);
    int lane = threadIdx.x & 31;
    int hA = lane >> 3, hB = hA + 4;
    int fj = (lane & 7) * 8;
    int beg = g_rowptr[n], end = g_rowptr[n + 1];
    int deg = end - beg;
    float er_l = (lane < 8) ? __ldg(&g_er[n * HH + lane]) : 0.f;

    float accA[8] = {}, accB[8] = {};
    float ssA = 0.f, ssB = 0.f;
#pragma unroll 2
    for (int i = 0; i < deg; i++) {
        int s = __ldg(&g_col[beg + i]);
        float p_mine = 0.f;
        if (lane < 8) {
            float e = __ldg(&g_el[s * HH + lane]) + er_l;
            e = e > 0.f ? e : 0.2f * e;
            p_mine = __expf(e);
        }
        float pA = __shfl_sync(0xffffffffu, p_mine, hA);
        float pB = __shfl_sync(0xffffffffu, p_mine, hB);
        const uint4* fr = (const uint4*)(g_feat + (size_t)s * CC) + lane;
        uint4 v0 = fr[0];
        uint4 v1 = fr[32];
        const __half2* h0 = (const __half2*)&v0;
        const __half2* h1 = (const __half2*)&v1;
#pragma unroll
        for (int q = 0; q < 4; q++) {
            float2 fa = __half22float2(h0[q]);
            accA[q * 2]     += pA * fa.x;
            accA[q * 2 + 1] += pA * fa.y;
            float2 fb = __half22float2(h1[q]);
            accB[q * 2]     += pB * fb.x;
            accB[q * 2 + 1] += pB * fb.y;
        }
        ssA += pA; ssB += pB;
    }
    float invA = (deg > 0) ? 1.f / ssA : 0.f;
    float invB = (deg > 0) ? 1.f / ssB : 0.f;

    float val[8];
#pragma unroll
    for (int k = 0; k < 8; k++)
        val[k] = accA[k] * invA + __ldg(&bias[hA * FF + fj + k])
               + accB[k] * invB + __ldg(&bias[hB * FF + fj + k]);
    // sum over the 4 hA-groups (lane bits 3,4) -> all 8 heads
#pragma unroll
    for (int o = 8; o <= 16; o <<= 1)
#pragma unroll
        for (int k = 0; k < 8; k++) val[k] += __shfl_xor_sync(0xffffffffu, val[k], o);

    if (lane < 8) {
        float4 o0, o1;
        o0.x = val[0] > 0.f ? val[0] : 0.01f * val[0];
        o0.y = val[1] > 0.f ? val[1] : 0.01f * val[1];
        o0.z = val[2] > 0.f ? val[2] : 0.01f * val[2];
        o0.w = val[3] > 0.f ? val[3] : 0.01f * val[3];
        o1.x = val[4] > 0.f ? val[4] : 0.01f * val[4];
        o1.y = val[5] > 0.f ? val[5] : 0.01f * val[5];
        o1.z = val[6] > 0.f ? val[6] : 0.01f * val[6];
        o1.w = val[7] > 0.f ? val[7] : 0.01f * val[7];
        float4* yp = (float4*)(y + (size_t)n * FF + lane * 8);
        yp[0] = o0;
        yp[1] = o1;
    }
}

// ---------------- launcher -------------------------------------------------
extern "C" void kernel_launch(void* const* d_in, const int* in_sizes, int n_in,
                              void* d_out, int out_size) {
    const float* x   = (const float*)d_in[0];
    const int*   src = (const int*)d_in[1];
    const int*   dst = (const int*)d_in[2];
    const float* W1  = (const float*)d_in[3];
    const float* al1 = (const float*)d_in[4];
    const float* ar1 = (const float*)d_in[5];
    const float* b1  = (const float*)d_in[6];
    const float* W2  = (const float*)d_in[7];
    const float* al2 = (const float*)d_in[8];
    const float* ar2 = (const float*)d_in[9];
    const float* b2  = (const float*)d_in[10];
    const float* W3  = (const float*)d_in[11];
    const float* al3 = (const float*)d_in[12];
    const float* ar3 = (const float*)d_in[13];
    const float* b3  = (const float*)d_in[14];
    const float* Wm  = (const float*)d_in[15];
    const float* bm  = (const float*)d_in[16];
    float* out = (float*)d_out;

    __half* feat_p;
    float* h_p;
    void *cnt_p, *fill_p;
    cudaGetSymbolAddress((void**)&feat_p, g_feat);
    cudaGetSymbolAddress((void**)&h_p, g_h);
    cudaGetSymbolAddress(&cnt_p, g_cnt);
    cudaGetSymbolAddress(&fill_p, g_fill);

    // CSR by dst (rebuilt every call; identical work each time)
    cudaMemsetAsync(cnt_p, 0, NN * sizeof(int));
    cudaMemsetAsync(fill_p, 0, NN * sizeof(int));
    k_hist<<<(EE + 255) / 256, 256>>>(dst);
    k_scan<<<1, 1024>>>();
    k_scatter<<<(EE + 255) / 256, 256>>>(src, dst);

    dim3 gproj(CC / 64, (NN + 127) / 128);

    // layer 1 (K=128)
    k_gemm_tc<__half><<<gproj, 256>>>(x, W1, nullptr, feat_p, al1, ar1, NN, CC, 128);
    k_agg<<<NN / 8, 256>>>(b1, h_p);

    // layer 2 (K=64)
    k_gemm_tc<__half><<<gproj, 256>>>(h_p, W2, nullptr, feat_p, al2, ar2, NN, CC, 64);
    k_agg<<<NN / 8, 256>>>(b2, h_p);

    // layer 3 (K=64)
    k_gemm_tc<__half><<<gproj, 256>>>(h_p, W3, nullptr, feat_p, al3, ar3, NN, CC, 64);
    k_agg<<<NN / 8, 256>>>(b3, h_p);

    // final linear: out = h @ Wm^T + bm  [N,OUT]
    k_gemm_tc<float><<<dim3(1, (NN + 127) / 128), 256>>>(h_p, Wm, bm, out,
                                                         nullptr, nullptr, NN, FF, FF);
}

// round 14
// speedup vs baseline: 1.3445x; 1.0312x over previous
#include <cuda_runtime.h>
#include <cuda_fp16.h>
#include <cstdint>

#define NN 50000
#define EE 800000
#define CC 512     // H*HID
#define HH 8
#define FF 64

// ---------------- scratch (device globals; no allocation allowed) ----------
__device__ __half g_feat[(size_t)NN * CC];  // 51.2 MB projected features (fp16)
__device__ float g_el[NN * HH];
__device__ float g_er[NN * HH];
__device__ float g_h[NN * FF];              // layer activations (fp32)
__device__ int   g_rowptr[NN + 1];
__device__ int   g_cnt[NN];
__device__ int   g_fill[NN];
__device__ int   g_col[EE];                 // src ids grouped by dst (CSR order)

// ---------------- CSR build ------------------------------------------------
__global__ void k_hist(const int* __restrict__ dst) {
    int e = blockIdx.x * blockDim.x + threadIdx.x;
    if (e < EE) atomicAdd(&g_cnt[dst[e]], 1);
}

__global__ void k_scan() {
    __shared__ int sh[1024];
    __shared__ int s_off;
    int tid = threadIdx.x;
    if (tid == 0) s_off = 0;
    __syncthreads();
    for (int base = 0; base < NN; base += 1024) {
        int idx = base + tid;
        int orig = (idx < NN) ? g_cnt[idx] : 0;
        int v = orig;
        sh[tid] = v;
        __syncthreads();
        for (int off = 1; off < 1024; off <<= 1) {
            int add = (tid >= off) ? sh[tid - off] : 0;
            __syncthreads();
            v += add; sh[tid] = v;
            __syncthreads();
        }
        int myoff = s_off;
        if (idx < NN) g_rowptr[idx] = myoff + (v - orig);
        __syncthreads();
        if (tid == 1023) s_off = myoff + v;
        __syncthreads();
    }
    if (tid == 0) g_rowptr[NN] = s_off;
}

__global__ void k_scatter(const int* __restrict__ src, const int* __restrict__ dst) {
    int e = blockIdx.x * blockDim.x + threadIdx.x;
    if (e < EE) {
        int d = dst[e];
        int pos = g_rowptr[d] + atomicAdd(&g_fill[d], 1);
        g_col[pos] = src[e];
    }
}

// ---------------- fp16 tensor-core GEMM + fused el/er ----------------------
// C[M,NCol] = A[M,K] @ B[NCol,K]^T (+bias). Block tile 128x128, 8 warps
// (4M x 2N), warp tile 32x64, mma m16n8k16, double-buffered fragment smem
// (one __syncthreads per 32-K slab). If al != nullptr: each 64-col half of
// the block is one head; warp wn computes el/er for its head warp-locally.
__device__ __forceinline__ uint32_t pk(float x, float y) {
    __half2 h = __floats2half2_rn(x, y);
    return *reinterpret_cast<uint32_t*>(&h);
}

__device__ __forceinline__ void store_c(float* C, size_t idx, float v) { C[idx] = v; }
__device__ __forceinline__ void store_c(__half* C, size_t idx, float v) { C[idx] = __float2half_rn(v); }

#define ABUF 2048   // u32 per As buffer (2 ks * 8 mt * 32 * 4)
#define BBUF 2048   // u32 per Bs buffer (2 ks * 16 nt * 32 * 2)

template <typename OutT>
__global__ __launch_bounds__(256, 2) void k_gemm_tc(
    const float* __restrict__ A, const float* __restrict__ B,
    const float* __restrict__ bias, OutT* __restrict__ C,
    const float* __restrict__ al, const float* __restrict__ ar,
    int M, int NCol, int K)
{
    __shared__ uint32_t As2[2 * ABUF];   // 16 KB (double-buffered)
    __shared__ uint32_t Bs2[2 * BBUF];   // 16 KB
    const int tid = threadIdx.x;
    const int lane = tid & 31, wid = tid >> 5;
    const int wm = wid & 3, wn = wid >> 2;
    const int m0 = blockIdx.y * 128, n0 = blockIdx.x * 128;

    float acc[2][8][4];
#pragma unroll
    for (int im = 0; im < 2; im++)
#pragma unroll
        for (int in = 0; in < 8; in++)
#pragma unroll
            for (int q = 0; q < 4; q++) acc[im][in][q] = 0.f;

    float4 rA[4], rB[4];

    // ---- load slab 0 into regs ----
#pragma unroll
    for (int i = 0; i < 4; i++) {
        int idx = tid + 256 * i;
        int row = idx >> 3, c0 = (idx & 7) << 2;
        int gr = m0 + row;
        rA[i] = (gr < M) ? *(const float4*)(A + (size_t)gr * K + c0)
                         : make_float4(0.f, 0.f, 0.f, 0.f);
        int gc = n0 + row;
        rB[i] = (gc < NCol) ? *(const float4*)(B + (size_t)gc * K + c0)
                            : make_float4(0.f, 0.f, 0.f, 0.f);
    }
    // ---- stage slab 0 into buffer 0 ----
#pragma unroll
    for (int i = 0; i < 4; i++) {
        int idx = tid + 256 * i;
        int row = idx >> 3, c0 = (idx & 7) << 2;
        int ks = c0 >> 4, ck = c0 & 15;
        int q0 = ck >> 3, tig0 = (ck & 7) >> 1;
        {   // A
            int mt = row >> 4, rr = row & 15;
            int q1 = rr >> 3, gid = rr & 7;
            int reg = (q1 + 2 * q0) ^ (ks << 1);
            int sb = ((ks * 8 + mt) * 32 + gid * 4);
            As2[(sb + tig0) * 4 + reg]     = pk(rA[i].x, rA[i].y);
            As2[(sb + tig0 + 1) * 4 + reg] = pk(rA[i].z, rA[i].w);
        }
        {   // B
            int nt = row >> 3, gid = row & 7;
            int l0 = gid * 4 + tig0;
            int base = (ks * 16 + nt) * 32;
            Bs2[(base + ((l0 + ks * 2) & 31)) * 2 + q0]     = pk(rB[i].x, rB[i].y);
            Bs2[(base + ((l0 + 1 + ks * 2) & 31)) * 2 + q0] = pk(rB[i].z, rB[i].w);
        }
    }
    __syncthreads();

    const int nslab = K >> 5;
    for (int it = 0; it < nslab; it++) {
        int cur = it & 1;
        // ---- prefetch next slab into regs (hidden under mma) ----
        if (it + 1 < nslab) {
            int kt = (it + 1) << 5;
#pragma unroll
            for (int i = 0; i < 4; i++) {
                int idx = tid + 256 * i;
                int row = idx >> 3, c0 = (idx & 7) << 2;
                int gr = m0 + row;
                rA[i] = (gr < M) ? *(const float4*)(A + (size_t)gr * K + kt + c0)
                                 : make_float4(0.f, 0.f, 0.f, 0.f);
                int gc = n0 + row;
                rB[i] = (gc < NCol) ? *(const float4*)(B + (size_t)gc * K + kt + c0)
                                    : make_float4(0.f, 0.f, 0.f, 0.f);
            }
        }

        // ---- compute: 2 ksteps x (2 im x 8 in) mma ----
        const uint32_t* Ab = As2 + cur * ABUF;
        const uint32_t* Bb = Bs2 + cur * BBUF;
#pragma unroll
        for (int ks = 0; ks < 2; ks++) {
            uint32_t a[2][4];
#pragma unroll
            for (int im = 0; im < 2; im++) {
                uint4 v = *(const uint4*)(Ab + ((ks * 8 + wm * 2 + im) * 32 + lane) * 4);
                uint32_t vc[4] = {v.x, v.y, v.z, v.w};
#pragma unroll
                for (int j = 0; j < 4; j++) a[im][j] = vc[j ^ (ks << 1)];
            }
#pragma unroll
            for (int half = 0; half < 2; half++) {
                uint32_t b[4][2];
#pragma unroll
                for (int i4 = 0; i4 < 4; i4++) {
                    int in = half * 4 + i4;
                    uint2 u = *(const uint2*)(Bb + ((ks * 16 + wn * 8 + in) * 32 + ((lane + ks * 2) & 31)) * 2);
                    b[i4][0] = u.x; b[i4][1] = u.y;
                }
#pragma unroll
                for (int im = 0; im < 2; im++)
#pragma unroll
                    for (int i4 = 0; i4 < 4; i4++)
                        asm volatile(
                            "mma.sync.aligned.m16n8k16.row.col.f32.f16.f16.f32 "
                            "{%0,%1,%2,%3},{%4,%5,%6,%7},{%8,%9},{%0,%1,%2,%3};"
                            : "+f"(acc[im][half * 4 + i4][0]), "+f"(acc[im][half * 4 + i4][1]),
                              "+f"(acc[im][half * 4 + i4][2]), "+f"(acc[im][half * 4 + i4][3])
                            : "r"(a[im][0]), "r"(a[im][1]), "r"(a[im][2]), "r"(a[im][3]),
                              "r"(b[i4][0]), "r"(b[i4][1]));
            }
        }

        // ---- stage next slab into the other buffer ----
        if (it + 1 < nslab) {
            uint32_t* Aw = As2 + (cur ^ 1) * ABUF;
            uint32_t* Bw = Bs2 + (cur ^ 1) * BBUF;
#pragma unroll
            for (int i = 0; i < 4; i++) {
                int idx = tid + 256 * i;
                int row = idx >> 3, c0 = (idx & 7) << 2;
                int ks = c0 >> 4, ck = c0 & 15;
                int q0 = ck >> 3, tig0 = (ck & 7) >> 1;
                {
                    int mt = row >> 4, rr = row & 15;
                    int q1 = rr >> 3, gid = rr & 7;
                    int reg = (q1 + 2 * q0) ^ (ks << 1);
                    int sb = ((ks * 8 + mt) * 32 + gid * 4);
                    Aw[(sb + tig0) * 4 + reg]     = pk(rA[i].x, rA[i].y);
                    Aw[(sb + tig0 + 1) * 4 + reg] = pk(rA[i].z, rA[i].w);
                }
                {
                    int nt = row >> 3, gid = row & 7;
                    int l0 = gid * 4 + tig0;
                    int base = (ks * 16 + nt) * 32;
                    Bw[(base + ((l0 + ks * 2) & 31)) * 2 + q0]     = pk(rB[i].x, rB[i].y);
                    Bw[(base + ((l0 + 1 + ks * 2) & 31)) * 2 + q0] = pk(rB[i].z, rB[i].w);
                }
            }
            __syncthreads();
        }
    }

    // ---- epilogue: store C ----
    int gid = lane >> 2, tig = lane & 3;
#pragma unroll
    for (int im = 0; im < 2; im++) {
        int r = m0 + wm * 32 + im * 16 + gid;
#pragma unroll
        for (int in = 0; in < 8; in++) {
            int c = n0 + wn * 64 + in * 8 + tig * 2;
            if (c < NCol) {
                float b0v = bias ? bias[c] : 0.f;
                float b1v = bias ? bias[c + 1] : 0.f;
                if (r < M) {
                    store_c(C, (size_t)r * NCol + c,     acc[im][in][0] + b0v);
                    store_c(C, (size_t)r * NCol + c + 1, acc[im][in][1] + b1v);
                }
                if (r + 8 < M) {
                    store_c(C, (size_t)(r + 8) * NCol + c,     acc[im][in][2] + b0v);
                    store_c(C, (size_t)(r + 8) * NCol + c + 1, acc[im][in][3] + b1v);
                }
            }
        }
    }

    // ---- fused el/er: warp wn owns head (blockIdx.x*2 + wn) entirely ----
    if (al != nullptr) {
        int head = blockIdx.x * 2 + wn;
        const float* alh = al + head * FF;
        const float* arh = ar + head * FF;
        float sl[2][2] = {}, sr[2][2] = {};
#pragma unroll
        for (int im = 0; im < 2; im++)
#pragma unroll
            for (int in = 0; in < 8; in++) {
                int cc0 = in * 8 + tig * 2;       // col within head
                float a0 = alh[cc0], a1 = alh[cc0 + 1];
                float r0 = arh[cc0], r1 = arh[cc0 + 1];
                sl[im][0] += acc[im][in][0] * a0 + acc[im][in][1] * a1;
                sl[im][1] += acc[im][in][2] * a0 + acc[im][in][3] * a1;
                sr[im][0] += acc[im][in][0] * r0 + acc[im][in][1] * r1;
                sr[im][1] += acc[im][in][2] * r0 + acc[im][in][3] * r1;
            }
#pragma unroll
        for (int o = 1; o <= 2; o <<= 1)
#pragma unroll
            for (int im = 0; im < 2; im++)
#pragma unroll
                for (int hq = 0; hq < 2; hq++) {
                    sl[im][hq] += __shfl_xor_sync(0xffffffffu, sl[im][hq], o);
                    sr[im][hq] += __shfl_xor_sync(0xffffffffu, sr[im][hq], o);
                }
        if (tig == 0) {
#pragma unroll
            for (int im = 0; im < 2; im++) {
                int r = m0 + wm * 32 + im * 16 + gid;
                if (r < M) {
                    g_el[r * HH + head] = sl[im][0];
                    g_er[r * HH + head] = sr[im][0];
                }
                if (r + 8 < M) {
                    g_el[(r + 8) * HH + head] = sl[im][1];
                    g_er[(r + 8) * HH + head] = sr[im][1];
                }
            }
        }
    }
}

// ---------------- aggregate: warp per node, all 8 heads in-warp ------------
__global__ __launch_bounds__(256) void k_agg(const float* __restrict__ bias, float* __restrict__ y) {
    int n = blockIdx.x * 8 + (threadIdx.x >> 5);
    int lane = threadIdx.x & 31;
    int hA = lane >> 3, hB = hA + 4;
    int fj = (lane & 7) * 8;
    int beg = g_rowptr[n], end = g_rowptr[n + 1];
    int deg = end - beg;
    float er_l = (lane < 8) ? __ldg(&g_er[n * HH + lane]) : 0.f;

    float accA[8] = {}, accB[8] = {};
    float ssA = 0.f, ssB = 0.f;
#pragma unroll 2
    for (int i = 0; i < deg; i++) {
        int s = __ldg(&g_col[beg + i]);
        float p_mine = 0.f;
        if (lane < 8) {
            float e = __ldg(&g_el[s * HH + lane]) + er_l;
            e = e > 0.f ? e : 0.2f * e;
            p_mine = __expf(e);
        }
        float pA = __shfl_sync(0xffffffffu, p_mine, hA);
        float pB = __shfl_sync(0xffffffffu, p_mine, hB);
        const uint4* fr = (const uint4*)(g_feat + (size_t)s * CC) + lane;
        uint4 v0 = fr[0];
        uint4 v1 = fr[32];
        const __half2* h0 = (const __half2*)&v0;
        const __half2* h1 = (const __half2*)&v1;
#pragma unroll
        for (int q = 0; q < 4; q++) {
            float2 fa = __half22float2(h0[q]);
            accA[q * 2]     += pA * fa.x;
            accA[q * 2 + 1] += pA * fa.y;
            float2 fb = __half22float2(h1[q]);
            accB[q * 2]     += pB * fb.x;
            accB[q * 2 + 1] += pB * fb.y;
        }
        ssA += pA; ssB += pB;
    }
    float invA = (deg > 0) ? 1.f / ssA : 0.f;
    float invB = (deg > 0) ? 1.f / ssB : 0.f;

    float val[8];
#pragma unroll
    for (int k = 0; k < 8; k++)
        val[k] = accA[k] * invA + __ldg(&bias[hA * FF + fj + k])
               + accB[k] * invB + __ldg(&bias[hB * FF + fj + k]);
#pragma unroll
    for (int o = 8; o <= 16; o <<= 1)
#pragma unroll
        for (int k = 0; k < 8; k++) val[k] += __shfl_xor_sync(0xffffffffu, val[k], o);

    if (lane < 8) {
        float4 o0, o1;
        o0.x = val[0] > 0.f ? val[0] : 0.01f * val[0];
        o0.y = val[1] > 0.f ? val[1] : 0.01f * val[1];
        o0.z = val[2] > 0.f ? val[2] : 0.01f * val[2];
        o0.w = val[3] > 0.f ? val[3] : 0.01f * val[3];
        o1.x = val[4] > 0.f ? val[4] : 0.01f * val[4];
        o1.y = val[5] > 0.f ? val[5] : 0.01f * val[5];
        o1.z = val[6] > 0.f ? val[6] : 0.01f * val[6];
        o1.w = val[7] > 0.f ? val[7] : 0.01f * val[7];
        float4* yp = (float4*)(y + (size_t)n * FF + lane * 8);
        yp[0] = o0;
        yp[1] = o1;
    }
}

// ---------------- launcher -------------------------------------------------
extern "C" void kernel_launch(void* const* d_in, const int* in_sizes, int n_in,
                              void* d_out, int out_size) {
    const float* x   = (const float*)d_in[0];
    const int*   src = (const int*)d_in[1];
    const int*   dst = (const int*)d_in[2];
    const float* W1  = (const float*)d_in[3];
    const float* al1 = (const float*)d_in[4];
    const float* ar1 = (const float*)d_in[5];
    const float* b1  = (const float*)d_in[6];
    const float* W2  = (const float*)d_in[7];
    const float* al2 = (const float*)d_in[8];
    const float* ar2 = (const float*)d_in[9];
    const float* b2  = (const float*)d_in[10];
    const float* W3  = (const float*)d_in[11];
    const float* al3 = (const float*)d_in[12];
    const float* ar3 = (const float*)d_in[13];
    const float* b3  = (const float*)d_in[14];
    const float* Wm  = (const float*)d_in[15];
    const float* bm  = (const float*)d_in[16];
    float* out = (float*)d_out;

    __half* feat_p;
    float* h_p;
    void *cnt_p, *fill_p;
    cudaGetSymbolAddress((void**)&feat_p, g_feat);
    cudaGetSymbolAddress((void**)&h_p, g_h);
    cudaGetSymbolAddress(&cnt_p, g_cnt);
    cudaGetSymbolAddress(&fill_p, g_fill);

    // CSR by dst (rebuilt every call; identical work each time)
    cudaMemsetAsync(cnt_p, 0, NN * sizeof(int));
    cudaMemsetAsync(fill_p, 0, NN * sizeof(int));
    k_hist<<<(EE + 255) / 256, 256>>>(dst);
    k_scan<<<1, 1024>>>();
    k_scatter<<<(EE + 255) / 256, 256>>>(src, dst);

    dim3 gproj(CC / 128, (NN + 127) / 128);

    // layer 1 (K=128)
    k_gemm_tc<__half><<<gproj, 256>>>(x, W1, nullptr, feat_p, al1, ar1, NN, CC, 128);
    k_agg<<<NN / 8, 256>>>(b1, h_p);

    // layer 2 (K=64)
    k_gemm_tc<__half><<<gproj, 256>>>(h_p, W2, nullptr, feat_p, al2, ar2, NN, CC, 64);
    k_agg<<<NN / 8, 256>>>(b2, h_p);

    // layer 3 (K=64)
    k_gemm_tc<__half><<<gproj, 256>>>(h_p, W3, nullptr, feat_p, al3, ar3, NN, CC, 64);
    k_agg<<<NN / 8, 256>>>(b3, h_p);

    // final linear: out = h @ Wm^T + bm  [N,OUT]
    k_gemm_tc<float><<<dim3(1, (NN + 127) / 128), 256>>>(h_p, Wm, bm, out,
                                                         nullptr, nullptr, NN, FF, FF);
}

// round 16
// speedup vs baseline: 1.4050x; 1.0450x over previous
#include <cuda_runtime.h>
#include <cuda_fp16.h>
#include <cstdint>

#define NN 50000
#define EE 800000
#define CC 512     // H*HID
#define HH 8
#define FF 64

// ---------------- scratch (device globals; no allocation allowed) ----------
__device__ __align__(16) __half g_feat[(size_t)NN * CC];  // 51.2 MB fp16 features
__device__ float g_el[NN * HH];
__device__ float g_er[NN * HH];
__device__ __align__(16) __half g_h[NN * FF];             // activations (fp16)
__device__ __align__(16) __half g_xh[(size_t)NN * 128];   // x converted
__device__ __align__(16) __half g_w1h[CC * 128];
__device__ __align__(16) __half g_w2h[CC * FF];
__device__ __align__(16) __half g_w3h[CC * FF];
__device__ __align__(16) __half g_wmh[FF * FF];
__device__ int   g_rowptr[NN + 1];
__device__ int   g_cnt[NN];
__device__ int   g_fill[NN];
__device__ int   g_col[EE];

// ---------------- fp32 -> fp16 convert -------------------------------------
__global__ void k_cvt(const float* __restrict__ in, __half* __restrict__ out, int n4) {
    int i = blockIdx.x * blockDim.x + threadIdx.x;
    if (i < n4) {
        float4 v = ((const float4*)in)[i];
        __half2 h0 = __floats2half2_rn(v.x, v.y);
        __half2 h1 = __floats2half2_rn(v.z, v.w);
        uint2 u;
        u.x = *(uint32_t*)&h0;
        u.y = *(uint32_t*)&h1;
        ((uint2*)out)[i] = u;
    }
}

// ---------------- CSR build ------------------------------------------------
__global__ void k_hist(const int* __restrict__ dst) {
    int e = blockIdx.x * blockDim.x + threadIdx.x;
    if (e < EE) atomicAdd(&g_cnt[dst[e]], 1);
}

__global__ void k_scan() {
    __shared__ int sh[1024];
    __shared__ int s_off;
    int tid = threadIdx.x;
    if (tid == 0) s_off = 0;
    __syncthreads();
    for (int base = 0; base < NN; base += 1024) {
        int idx = base + tid;
        int orig = (idx < NN) ? g_cnt[idx] : 0;
        int v = orig;
        sh[tid] = v;
        __syncthreads();
        for (int off = 1; off < 1024; off <<= 1) {
            int add = (tid >= off) ? sh[tid - off] : 0;
            __syncthreads();
            v += add; sh[tid] = v;
            __syncthreads();
        }
        int myoff = s_off;
        if (idx < NN) g_rowptr[idx] = myoff + (v - orig);
        __syncthreads();
        if (tid == 1023) s_off = myoff + v;
        __syncthreads();
    }
    if (tid == 0) g_rowptr[NN] = s_off;
}

__global__ void k_scatter(const int* __restrict__ src, const int* __restrict__ dst) {
    int e = blockIdx.x * blockDim.x + threadIdx.x;
    if (e < EE) {
        int d = dst[e];
        int pos = g_rowptr[d] + atomicAdd(&g_fill[d], 1);
        g_col[pos] = src[e];
    }
}

// ---------------- fp16 GEMM via ldmatrix + mma m16n8k16 --------------------
// C[M,NCol] = A[M,K] @ B[NCol,K]^T (+bias); A,B fp16. Block 128x128, 8 warps
// (4M x 2N), warp tile 32x64. Tiles stored row-major 64B/row with swizzle
// unit ^= (row>>1)&3; fragments via ldmatrix.x4 (loop-invariant addresses).
// If al != nullptr: 64-col half == one head; warp wn emits el/er warp-locally.
__device__ __forceinline__ void store_c(float* C, size_t idx, float v) { C[idx] = v; }
__device__ __forceinline__ void store_c(__half* C, size_t idx, float v) { C[idx] = __float2half_rn(v); }

#define LDSM4(r0, r1, r2, r3, addr) \
    asm volatile("ldmatrix.sync.aligned.m8n8.x4.shared.b16 {%0,%1,%2,%3}, [%4];" \
                 : "=r"(r0), "=r"(r1), "=r"(r2), "=r"(r3) : "r"(addr))

template <typename OutT>
__global__ __launch_bounds__(256, 2) void k_gemm_tc(
    const __half* __restrict__ A, const __half* __restrict__ B,
    const float* __restrict__ bias, OutT* __restrict__ C,
    const float* __restrict__ al, const float* __restrict__ ar,
    int M, int NCol, int K)
{
    // [A0 8K][B0 8K][A1 8K][B1 8K] ; buffer toggle = +16384 bytes
    __shared__ __align__(16) uint8_t smem[32768];
    const int tid = threadIdx.x;
    const int lane = tid & 31, wid = tid >> 5;
    const int wm = wid & 3, wn = wid >> 2;
    const int m0 = blockIdx.y * 128, n0 = blockIdx.x * 128;
    const uint32_t sbase = (uint32_t)__cvta_generic_to_shared(smem);

    float acc[2][8][4];
#pragma unroll
    for (int im = 0; im < 2; im++)
#pragma unroll
        for (int in = 0; in < 8; in++)
#pragma unroll
            for (int q = 0; q < 4; q++) acc[im][in][q] = 0.f;

    // ---- per-thread staging descriptors (loop-invariant) ----
    int rowS[2], sOff[2];           // smem byte offset within a tile
    size_t gA[2], gB[2];
    bool vA[2], vB[2];
#pragma unroll
    for (int i = 0; i < 2; i++) {
        int idx = tid + 256 * i;
        int row = idx >> 2, c0h = (idx & 3) * 8;
        rowS[i] = row;
        int u = c0h >> 3;
        sOff[i] = row * 64 + ((u ^ ((row >> 1) & 3)) << 4);
        vA[i] = (m0 + row) < M;
        vB[i] = (n0 + row) < NCol;
        gA[i] = (size_t)(m0 + row) * K + c0h;
        gB[i] = (size_t)(n0 + row) * K + c0h;
    }

    // ---- per-warp ldmatrix addresses (ks=0; ks=1 -> XOR 32) ----
    uint32_t aAddr[2], bAddr[4];
    {
        int rl = (lane & 7) + ((lane >> 3) & 1) * 8;
        int uA = lane >> 4;
#pragma unroll
        for (int im = 0; im < 2; im++) {
            int r = wm * 32 + im * 16 + rl;
            aAddr[im] = r * 64 + ((uA ^ ((r >> 1) & 3)) << 4);
        }
#pragma unroll
        for (int ip = 0; ip < 4; ip++) {
            int r = wn * 64 + ip * 16 + rl;
            bAddr[ip] = 8192 + r * 64 + ((uA ^ ((r >> 1) & 3)) << 4);
        }
    }

    uint4 rA[2], rB[2];
    const uint4 z4 = make_uint4(0, 0, 0, 0);
    // ---- load + stage slab 0 ----
#pragma unroll
    for (int i = 0; i < 2; i++) {
        rA[i] = vA[i] ? *(const uint4*)(A + gA[i]) : z4;
        rB[i] = vB[i] ? *(const uint4*)(B + gB[i]) : z4;
    }
#pragma unroll
    for (int i = 0; i < 2; i++) {
        *(uint4*)(smem + sOff[i]) = rA[i];
        *(uint4*)(smem + 8192 + sOff[i]) = rB[i];
    }
    __syncthreads();

    const int nslab = K >> 5;
    for (int it = 0; it < nslab; it++) {
        // prefetch next slab into regs
        if (it + 1 < nslab) {
            int kt = (it + 1) << 5;
#pragma unroll
            for (int i = 0; i < 2; i++) {
                rA[i] = vA[i] ? *(const uint4*)(A + gA[i] + kt) : z4;
                rB[i] = vB[i] ? *(const uint4*)(B + gB[i] + kt) : z4;
            }
        }

        const uint32_t bb = sbase + ((it & 1) << 14);
#pragma unroll
        for (int ks = 0; ks < 2; ks++) {
            const uint32_t kx = ks << 5;
            uint32_t a[2][4];
#pragma unroll
            for (int im = 0; im < 2; im++)
                LDSM4(a[im][0], a[im][1], a[im][2], a[im][3], bb + (aAddr[im] ^ kx));
#pragma unroll
            for (int ip = 0; ip < 4; ip++) {
                uint32_t r0, r1, r2, r3;
                LDSM4(r0, r1, r2, r3, bb + (bAddr[ip] ^ kx));
                // b(in=2ip) = {r0,r2}; b(in=2ip+1) = {r1,r3}
#pragma unroll
                for (int im = 0; im < 2; im++) {
                    asm volatile(
                        "mma.sync.aligned.m16n8k16.row.col.f32.f16.f16.f32 "
                        "{%0,%1,%2,%3},{%4,%5,%6,%7},{%8,%9},{%0,%1,%2,%3};"
                        : "+f"(acc[im][2 * ip][0]), "+f"(acc[im][2 * ip][1]),
                          "+f"(acc[im][2 * ip][2]), "+f"(acc[im][2 * ip][3])
                        : "r"(a[im][0]), "r"(a[im][1]), "r"(a[im][2]), "r"(a[im][3]),
                          "r"(r0), "r"(r2));
                    asm volatile(
                        "mma.sync.aligned.m16n8k16.row.col.f32.f16.f16.f32 "
                        "{%0,%1,%2,%3},{%4,%5,%6,%7},{%8,%9},{%0,%1,%2,%3};"
                        : "+f"(acc[im][2 * ip + 1][0]), "+f"(acc[im][2 * ip + 1][1]),
                          "+f"(acc[im][2 * ip + 1][2]), "+f"(acc[im][2 * ip + 1][3])
                        : "r"(a[im][0]), "r"(a[im][1]), "r"(a[im][2]), "r"(a[im][3]),
                          "r"(r1), "r"(r3));
                }
            }
        }

        // stage next slab
        if (it + 1 < nslab) {
            uint8_t* wbuf = smem + (((it + 1) & 1) << 14);
#pragma unroll
            for (int i = 0; i < 2; i++) {
                *(uint4*)(wbuf + sOff[i]) = rA[i];
                *(uint4*)(wbuf + 8192 + sOff[i]) = rB[i];
            }
            __syncthreads();
        }
    }

    // ---- epilogue: store C ----
    int gid = lane >> 2, tig = lane & 3;
#pragma unroll
    for (int im = 0; im < 2; im++) {
        int r = m0 + wm * 32 + im * 16 + gid;
#pragma unroll
        for (int in = 0; in < 8; in++) {
            int c = n0 + wn * 64 + in * 8 + tig * 2;
            if (c < NCol) {
                float b0v = bias ? bias[c] : 0.f;
                float b1v = bias ? bias[c + 1] : 0.f;
                if (r < M) {
                    store_c(C, (size_t)r * NCol + c,     acc[im][in][0] + b0v);
                    store_c(C, (size_t)r * NCol + c + 1, acc[im][in][1] + b1v);
                }
                if (r + 8 < M) {
                    store_c(C, (size_t)(r + 8) * NCol + c,     acc[im][in][2] + b0v);
                    store_c(C, (size_t)(r + 8) * NCol + c + 1, acc[im][in][3] + b1v);
                }
            }
        }
    }

    // ---- fused el/er: warp wn owns head (blockIdx.x*2 + wn) ----
    if (al != nullptr) {
        int head = blockIdx.x * 2 + wn;
        const float* alh = al + head * FF;
        const float* arh = ar + head * FF;
        float sl[2][2] = {}, sr[2][2] = {};
#pragma unroll
        for (int im = 0; im < 2; im++)
#pragma unroll
            for (int in = 0; in < 8; in++) {
                int cc0 = in * 8 + tig * 2;
                float a0 = alh[cc0], a1 = alh[cc0 + 1];
                float r0 = arh[cc0], r1 = arh[cc0 + 1];
                sl[im][0] += acc[im][in][0] * a0 + acc[im][in][1] * a1;
                sl[im][1] += acc[im][in][2] * a0 + acc[im][in][3] * a1;
                sr[im][0] += acc[im][in][0] * r0 + acc[im][in][1] * r1;
                sr[im][1] += acc[im][in][2] * r0 + acc[im][in][3] * r1;
            }
#pragma unroll
        for (int o = 1; o <= 2; o <<= 1)
#pragma unroll
            for (int im = 0; im < 2; im++)
#pragma unroll
                for (int hq = 0; hq < 2; hq++) {
                    sl[im][hq] += __shfl_xor_sync(0xffffffffu, sl[im][hq], o);
                    sr[im][hq] += __shfl_xor_sync(0xffffffffu, sr[im][hq], o);
                }
        if (tig == 0) {
#pragma unroll
            for (int im = 0; im < 2; im++) {
                int r = m0 + wm * 32 + im * 16 + gid;
                if (r < M) {
                    g_el[r * HH + head] = sl[im][0];
                    g_er[r * HH + head] = sr[im][0];
                }
                if (r + 8 < M) {
                    g_el[(r + 8) * HH + head] = sl[im][1];
                    g_er[(r + 8) * HH + head] = sr[im][1];
                }
            }
        }
    }
}

// ---------------- aggregate: warp per node, all 8 heads in-warp ------------
__global__ __launch_bounds__(256) void k_agg(const float* __restrict__ bias, __half* __restrict__ y) {
    int n = blockIdx.x * 8 + (threadIdx.x >> 5);
    int lane = threadIdx.x & 31;
    int hA = lane >> 3, hB = hA + 4;
    int fj = (lane & 7) * 8;
    int beg = g_rowptr[n], end = g_rowptr[n + 1];
    int deg = end - beg;
    float er_l = (lane < 8) ? __ldg(&g_er[n * HH + lane]) : 0.f;

    float accA[8] = {}, accB[8] = {};
    float ssA = 0.f, ssB = 0.f;
#pragma unroll 2
    for (int i = 0; i < deg; i++) {
        int s = __ldg(&g_col[beg + i]);
        float p_mine = 0.f;
        if (lane < 8) {
            float e = __ldg(&g_el[s * HH + lane]) + er_l;
            e = e > 0.f ? e : 0.2f * e;
            p_mine = __expf(e);
        }
        float pA = __shfl_sync(0xffffffffu, p_mine, hA);
        float pB = __shfl_sync(0xffffffffu, p_mine, hB);
        const uint4* fr = (const uint4*)(g_feat + (size_t)s * CC) + lane;
        uint4 v0 = fr[0];
        uint4 v1 = fr[32];
        const __half2* h0 = (const __half2*)&v0;
        const __half2* h1 = (const __half2*)&v1;
#pragma unroll
        for (int q = 0; q < 4; q++) {
            float2 fa = __half22float2(h0[q]);
            accA[q * 2]     += pA * fa.x;
            accA[q * 2 + 1] += pA * fa.y;
            float2 fb = __half22float2(h1[q]);
            accB[q * 2]     += pB * fb.x;
            accB[q * 2 + 1] += pB * fb.y;
        }
        ssA += pA; ssB += pB;
    }
    float invA = (deg > 0) ? 1.f / ssA : 0.f;
    float invB = (deg > 0) ? 1.f / ssB : 0.f;

    float val[8];
#pragma unroll
    for (int k = 0; k < 8; k++)
        val[k] = accA[k] * invA + __ldg(&bias[hA * FF + fj + k])
               + accB[k] * invB + __ldg(&bias[hB * FF + fj + k]);
#pragma unroll
    for (int o = 8; o <= 16; o <<= 1)
#pragma unroll
        for (int k = 0; k < 8; k++) val[k] += __shfl_xor_sync(0xffffffffu, val[k], o);

    if (lane < 8) {
        __half2 o2[4];
#pragma unroll
        for (int q = 0; q < 4; q++) {
            float v0 = val[q * 2],     l0 = v0 > 0.f ? v0 : 0.01f * v0;
            float v1 = val[q * 2 + 1], l1 = v1 > 0.f ? v1 : 0.01f * v1;
            o2[q] = __floats2half2_rn(l0, l1);
        }
        *(uint4*)(y + (size_t)n * FF + lane * 8) = *(uint4*)o2;
    }
}

// ---------------- launcher -------------------------------------------------
extern "C" void kernel_launch(void* const* d_in, const int* in_sizes, int n_in,
                              void* d_out, int out_size) {
    const float* x   = (const float*)d_in[0];
    const int*   src = (const int*)d_in[1];
    const int*   dst = (const int*)d_in[2];
    const float* W1  = (const float*)d_in[3];
    const float* al1 = (const float*)d_in[4];
    const float* ar1 = (const float*)d_in[5];
    const float* b1  = (const float*)d_in[6];
    const float* W2  = (const float*)d_in[7];
    const float* al2 = (const float*)d_in[8];
    const float* ar2 = (const float*)d_in[9];
    const float* b2  = (const float*)d_in[10];
    const float* W3  = (const float*)d_in[11];
    const float* al3 = (const float*)d_in[12];
    const float* ar3 = (const float*)d_in[13];
    const float* b3  = (const float*)d_in[14];
    const float* Wm  = (const float*)d_in[15];
    const float* bm  = (const float*)d_in[16];
    float* out = (float*)d_out;

    static cudaStream_t s2 = nullptr;
    static cudaEvent_t evF = nullptr, evJ = nullptr;
    if (s2 == nullptr) {
        cudaStreamCreateWithFlags(&s2, cudaStreamNonBlocking);
        cudaEventCreateWithFlags(&evF, cudaEventDisableTiming);
        cudaEventCreateWithFlags(&evJ, cudaEventDisableTiming);
    }

    __half *feat_p, *h_p, *xh_p, *w1_p, *w2_p, *w3_p, *wm_p;
    void *cnt_p, *fill_p;
    cudaGetSymbolAddress((void**)&feat_p, g_feat);
    cudaGetSymbolAddress((void**)&h_p, g_h);
    cudaGetSymbolAddress((void**)&xh_p, g_xh);
    cudaGetSymbolAddress((void**)&w1_p, g_w1h);
    cudaGetSymbolAddress((void**)&w2_p, g_w2h);
    cudaGetSymbolAddress((void**)&w3_p, g_w3h);
    cudaGetSymbolAddress((void**)&wm_p, g_wmh);
    cudaGetSymbolAddress(&cnt_p, g_cnt);
    cudaGetSymbolAddress(&fill_p, g_fill);

    // ---- fork: CSR build + later-layer weight converts on s2 ----
    cudaEventRecord(evF, 0);
    cudaStreamWaitEvent(s2, evF, 0);
    cudaMemsetAsync(cnt_p, 0, NN * sizeof(int), s2);
    cudaMemsetAsync(fill_p, 0, NN * sizeof(int), s2);
    k_hist<<<(EE + 255) / 256, 256, 0, s2>>>(dst);
    k_cvt<<<(CC * FF / 4 + 255) / 256, 256, 0, s2>>>(W2, w2_p, CC * FF / 4);
    k_cvt<<<(CC * FF / 4 + 255) / 256, 256, 0, s2>>>(W3, w3_p, CC * FF / 4);
    k_cvt<<<(FF * FF / 4 + 255) / 256, 256, 0, s2>>>(Wm, wm_p, FF * FF / 4);
    k_scan<<<1, 1024, 0, s2>>>();
    k_scatter<<<(EE + 255) / 256, 256, 0, s2>>>(src, dst);
    cudaEventRecord(evJ, s2);

    // ---- main stream: layer-1 projection chain ----
    k_cvt<<<(NN * 128 / 4 + 255) / 256, 256>>>(x, xh_p, NN * 128 / 4);
    k_cvt<<<(CC * 128 / 4 + 255) / 256, 256>>>(W1, w1_p, CC * 128 / 4);

    dim3 gproj(CC / 128, (NN + 127) / 128);
    k_gemm_tc<__half><<<gproj, 256>>>(xh_p, w1_p, nullptr, feat_p, al1, ar1, NN, CC, 128);
    cudaStreamWaitEvent(0, evJ, 0);
    k_agg<<<NN / 8, 256>>>(b1, h_p);

    // layer 2 (K=64)
    k_gemm_tc<__half><<<gproj, 256>>>(h_p, w2_p, nullptr, feat_p, al2, ar2, NN, CC, 64);
    k_agg<<<NN / 8, 256>>>(b2, h_p);

    // layer 3 (K=64)
    k_gemm_tc<__half><<<gproj, 256>>>(h_p, w3_p, nullptr, feat_p, al3, ar3, NN, CC, 64);
    k_agg<<<NN / 8, 256>>>(b3, h_p);

    // final linear: out = h @ Wm^T + bm  [N,OUT] fp32
    k_gemm_tc<float><<<dim3(1, (NN + 127) / 128), 256>>>(h_p, wm_p, bm, out,
                                                         nullptr, nullptr, NN, FF, FF);
}